// round 14
// baseline (speedup 1.0000x reference)
#include <cuda_runtime.h>
#include <cstdint>

// Problem constants
#define B_   2
#define T_   2048
#define DM_  2048
#define H_   16
#define Dh_  128
#define M_   (B_ * T_)          // 4096 rows for all GEMMs

// Scratch: Q, K, V, attn-out, each [B,H,T,D] (or [B*T, H*D]) = 8,388,608 floats.
__device__ float g_scratch[4ull * (size_t)B_ * H_ * T_ * Dh_];

// ---------------------------------------------------------------------------
// SGEMM: C[M,N] = A[M,K] @ W[K,N], M=4096, N=K=2048, fp32.
// 128x128 block tile, BK=8, 256 threads, 8x8 per-thread microtile,
// double-buffered smem, register-staged global prefetch.
// MODE 0: C row-major [M, N] (final output projection)
// MODE 1: scatter to [B, H, T, D] layout (QKV; each block-col = one head)
// ---------------------------------------------------------------------------
template<int MODE>
__global__ __launch_bounds__(256)
void sgemm_kernel(const float* __restrict__ A, const float* __restrict__ W,
                  float* __restrict__ C)
{
    constexpr int K  = DM_;        // 2048
    constexpr int N  = DM_;        // 2048
    constexpr int BK = 8;
    constexpr int NK = K / BK;     // 256

    __shared__ __align__(16) float As[2][BK][132];  // transposed A tile, padded
    __shared__ __align__(16) float Bs[2][BK][128];

    const int tid = threadIdx.x;
    const int m0  = blockIdx.y * 128;
    const int n0  = blockIdx.x * 128;

    // Global load mapping
    const int a_row = tid >> 1;           // 0..127
    const int a_col = (tid & 1) * 4;      // 0 or 4
    const int b_row = tid >> 5;           // 0..7
    const int b_col = (tid & 31) * 4;     // 0..124

    const float* Ap = A + (size_t)(m0 + a_row) * K + a_col;
    const float* Wp = W + (size_t)b_row * N + (n0 + b_col);

    // Preload tile 0
    float4 ar = *(const float4*)Ap;
    float4 br = *(const float4*)Wp;
    As[0][a_col + 0][a_row] = ar.x;
    As[0][a_col + 1][a_row] = ar.y;
    As[0][a_col + 2][a_row] = ar.z;
    As[0][a_col + 3][a_row] = ar.w;
    *(float4*)&Bs[0][b_row][b_col] = br;
    __syncthreads();

    const int tx = tid & 15, ty = tid >> 4;

    float acc[8][8];
    #pragma unroll
    for (int i = 0; i < 8; ++i)
        #pragma unroll
        for (int j = 0; j < 8; ++j) acc[i][j] = 0.f;

    for (int kt = 0; kt < NK; ++kt) {
        const int cur = kt & 1;
        if (kt + 1 < NK) {
            ar = *(const float4*)(Ap + (kt + 1) * BK);
            br = *(const float4*)(Wp + (size_t)(kt + 1) * BK * N);
        }
        #pragma unroll
        for (int k = 0; k < BK; ++k) {
            float a_[8], b_[8];
            *(float4*)(a_)     = *(const float4*)&As[cur][k][ty * 4];
            *(float4*)(a_ + 4) = *(const float4*)&As[cur][k][64 + ty * 4];
            *(float4*)(b_)     = *(const float4*)&Bs[cur][k][tx * 4];
            *(float4*)(b_ + 4) = *(const float4*)&Bs[cur][k][64 + tx * 4];
            #pragma unroll
            for (int i = 0; i < 8; ++i)
                #pragma unroll
                for (int j = 0; j < 8; ++j)
                    acc[i][j] = fmaf(a_[i], b_[j], acc[i][j]);
        }
        if (kt + 1 < NK) {
            const int nxt = cur ^ 1;
            As[nxt][a_col + 0][a_row] = ar.x;
            As[nxt][a_col + 1][a_row] = ar.y;
            As[nxt][a_col + 2][a_row] = ar.z;
            As[nxt][a_col + 3][a_row] = ar.w;
            *(float4*)&Bs[nxt][b_row][b_col] = br;
            __syncthreads();
        }
    }

    // Epilogue
    #pragma unroll
    for (int ih = 0; ih < 2; ++ih) {
        #pragma unroll
        for (int i = 0; i < 4; ++i) {
            const int r = m0 + ih * 64 + ty * 4 + i;
            #pragma unroll
            for (int jh = 0; jh < 2; ++jh) {
                const int c = n0 + jh * 64 + tx * 4;
                float4 v;
                v.x = acc[ih * 4 + i][jh * 4 + 0];
                v.y = acc[ih * 4 + i][jh * 4 + 1];
                v.z = acc[ih * 4 + i][jh * 4 + 2];
                v.w = acc[ih * 4 + i][jh * 4 + 3];
                if (MODE == 0) {
                    *(float4*)&C[(size_t)r * N + c] = v;
                } else {
                    const int b = r >> 11;           // T_ = 2048 = 2^11
                    const int t = r & (T_ - 1);
                    const int h = c >> 7;            // Dh_ = 128
                    const int d = c & (Dh_ - 1);
                    *(float4*)&C[(((size_t)(b * H_ + h)) * T_ + t) * Dh_ + d] = v;
                }
            }
        }
    }
}

// ---------------------------------------------------------------------------
// RoPE (in-place) on Q and K in [B,H,T,D] layout. Pair (j, j+64), j in [0,64).
// ---------------------------------------------------------------------------
__global__ __launch_bounds__(256)
void rope_kernel(float* __restrict__ Qm, float* __restrict__ Km,
                 const float* __restrict__ cosT, const float* __restrict__ sinT)
{
    const int idx = blockIdx.x * 256 + threadIdx.x;
    constexpr int PT = B_ * H_ * T_ * 64;          // pairs per tensor
    float* X = (idx < PT) ? Qm : Km;
    const int i  = (idx < PT) ? idx : idx - PT;
    const int j  = i & 63;
    const int t  = (i >> 6) & (T_ - 1);
    const int bh = i >> 17;                        // 2048*64 = 2^17
    const float c = cosT[t * 64 + j];
    const float s = sinT[t * 64 + j];
    const size_t base = ((size_t)bh * T_ + t) * Dh_;
    const float x1 = X[base + j];
    const float x2 = X[base + 64 + j];
    X[base + j]      = fmaf(x1, c, -x2 * s);
    X[base + 64 + j] = fmaf(x1, s,  x2 * c);
}

// ---------------------------------------------------------------------------
// Flash attention, fp32, causal. One block per (q-tile of 64, b*h).
// 256 threads: 16x16 grid; S microtile 4x4 per thread, O microtile 4x8.
// Online softmax stats replicated in registers across each 16-lane row group.
// ---------------------------------------------------------------------------
#define FPAD 68   // padded minor dim for transposed Q/K tiles (16B-aligned rows)
#define PPAD 65   // padded minor dim for transposed P tile

__global__ __launch_bounds__(256, 1)
void flash_kernel(const float* __restrict__ Q, const float* __restrict__ K,
                  const float* __restrict__ V, float* __restrict__ O)
{
    extern __shared__ __align__(16) float sm[];
    float* Qt = sm;                       // [128][FPAD]  (Q^T: [d][q])
    float* Kt = Qt + 128 * FPAD;          // [128][FPAD]  (K^T: [d][k])
    float* Vs = Kt + 128 * FPAD;          // [64][128]    (V row-major)
    float* Pt = Vs + 64 * 128;            // [64][PPAD]   (P^T: [k][q])

    const int tid = threadIdx.x;
    const int tx  = tid & 15, ty = tid >> 4;
    const int ty4 = ty * 4, tx4 = tx * 4, tx8 = tx * 8;
    const int q0  = blockIdx.x * 64;
    const int bh  = blockIdx.y;
    const float* Qb = Q + (size_t)bh * T_ * Dh_;
    const float* Kb = K + (size_t)bh * T_ * Dh_;
    const float* Vb = V + (size_t)bh * T_ * Dh_;

    // Load Q tile transposed into smem
    {
        const int row = tid >> 2, c4 = tid & 3;
        #pragma unroll
        for (int it = 0; it < 8; ++it) {
            const int col = (c4 + it * 4) * 4;
            float4 v = *(const float4*)(Qb + (size_t)(q0 + row) * Dh_ + col);
            Qt[(col + 0) * FPAD + row] = v.x;
            Qt[(col + 1) * FPAD + row] = v.y;
            Qt[(col + 2) * FPAD + row] = v.z;
            Qt[(col + 3) * FPAD + row] = v.w;
        }
    }

    float m_i[4], l_i[4], o[4][8];
    #pragma unroll
    for (int i = 0; i < 4; ++i) {
        m_i[i] = -1e30f; l_i[i] = 0.f;
        #pragma unroll
        for (int j = 0; j < 8; ++j) o[i][j] = 0.f;
    }

    const int   ntiles = blockIdx.x + 1;   // causal: kv tiles 0..qtile
    const float scale  = 0.08838834764831845f;   // 1/sqrt(128)

    for (int kt = 0; kt < ntiles; ++kt) {
        const int kv0 = kt * 64;
        __syncthreads();   // prior iter done reading Kt/Vs/Pt
        {
            const int row = tid >> 2, c4 = tid & 3;
            #pragma unroll
            for (int it = 0; it < 8; ++it) {
                const int col = (c4 + it * 4) * 4;
                float4 v = *(const float4*)(Kb + (size_t)(kv0 + row) * Dh_ + col);
                Kt[(col + 0) * FPAD + row] = v.x;
                Kt[(col + 1) * FPAD + row] = v.y;
                Kt[(col + 2) * FPAD + row] = v.z;
                Kt[(col + 3) * FPAD + row] = v.w;
            }
            const int vrow = tid >> 5, vc4 = (tid & 31) * 4;
            #pragma unroll
            for (int it = 0; it < 8; ++it) {
                float4 v = *(const float4*)(Vb + (size_t)(kv0 + vrow + it * 8) * Dh_ + vc4);
                *(float4*)&Vs[(vrow + it * 8) * Dh_ + vc4] = v;
            }
        }
        __syncthreads();

        // S = Q K^T (4x4 per thread over k=128)
        float s[4][4];
        #pragma unroll
        for (int i = 0; i < 4; ++i)
            #pragma unroll
            for (int j = 0; j < 4; ++j) s[i][j] = 0.f;

        #pragma unroll 4
        for (int kk = 0; kk < 128; ++kk) {
            float qv[4], kv[4];
            *(float4*)qv = *(const float4*)&Qt[kk * FPAD + ty4];
            *(float4*)kv = *(const float4*)&Kt[kk * FPAD + tx4];
            #pragma unroll
            for (int i = 0; i < 4; ++i)
                #pragma unroll
                for (int j = 0; j < 4; ++j)
                    s[i][j] = fmaf(qv[i], kv[j], s[i][j]);
        }

        // scale + causal mask (only the diagonal tile needs masking)
        const bool diag = (kv0 == q0);
        #pragma unroll
        for (int i = 0; i < 4; ++i)
            #pragma unroll
            for (int j = 0; j < 4; ++j) {
                float v = s[i][j] * scale;
                if (diag && (tx4 + j) > (ty4 + i)) v = -1e30f;
                s[i][j] = v;
            }

        // online softmax per row (reduce across the 16 lanes of a row group)
        #pragma unroll
        for (int i = 0; i < 4; ++i) {
            float mt = fmaxf(fmaxf(s[i][0], s[i][1]), fmaxf(s[i][2], s[i][3]));
            #pragma unroll
            for (int off = 8; off > 0; off >>= 1)
                mt = fmaxf(mt, __shfl_xor_sync(0xffffffffu, mt, off, 16));
            const float mnew = fmaxf(m_i[i], mt);
            float sum = 0.f;
            #pragma unroll
            for (int j = 0; j < 4; ++j) {
                const float p = __expf(s[i][j] - mnew);
                s[i][j] = p;
                sum += p;
            }
            #pragma unroll
            for (int off = 8; off > 0; off >>= 1)
                sum += __shfl_xor_sync(0xffffffffu, sum, off, 16);
            const float sc = __expf(m_i[i] - mnew);
            l_i[i] = l_i[i] * sc + sum;
            m_i[i] = mnew;
            #pragma unroll
            for (int j = 0; j < 8; ++j) o[i][j] *= sc;
        }

        // write P transposed
        #pragma unroll
        for (int j = 0; j < 4; ++j)
            #pragma unroll
            for (int i = 0; i < 4; ++i)
                Pt[(tx4 + j) * PPAD + ty4 + i] = s[i][j];
        __syncthreads();

        // O += P @ V  (4x8 per thread over kv=64)
        #pragma unroll 2
        for (int kk = 0; kk < 64; ++kk) {
            float p_[4], v_[8];
            #pragma unroll
            for (int i = 0; i < 4; ++i) p_[i] = Pt[kk * PPAD + ty4 + i];
            *(float4*)(v_)     = *(const float4*)&Vs[kk * Dh_ + tx8];
            *(float4*)(v_ + 4) = *(const float4*)&Vs[kk * Dh_ + tx8 + 4];
            #pragma unroll
            for (int i = 0; i < 4; ++i)
                #pragma unroll
                for (int j = 0; j < 8; ++j)
                    o[i][j] = fmaf(p_[i], v_[j], o[i][j]);
        }
    }

    // write O in [B, T, H*D] layout for the output projection GEMM
    const int b = bh >> 4, h = bh & (H_ - 1);
    #pragma unroll
    for (int i = 0; i < 4; ++i) {
        const float inv = 1.0f / l_i[i];
        const int t = q0 + ty4 + i;
        float* dst = O + ((size_t)(b * T_ + t)) * (H_ * Dh_) + h * Dh_ + tx8;
        float4 r0, r1;
        r0.x = o[i][0] * inv; r0.y = o[i][1] * inv;
        r0.z = o[i][2] * inv; r0.w = o[i][3] * inv;
        r1.x = o[i][4] * inv; r1.y = o[i][5] * inv;
        r1.z = o[i][6] * inv; r1.w = o[i][7] * inv;
        *(float4*)dst       = r0;
        *(float4*)(dst + 4) = r1;
    }
}

// ---------------------------------------------------------------------------
// Launch: QKV GEMMs -> RoPE -> flash attention -> output GEMM.
// Graph-capturable: kernel launches + host-side queries only.
// ---------------------------------------------------------------------------
extern "C" void kernel_launch(void* const* d_in, const int* in_sizes, int n_in,
                              void* d_out, int out_size)
{
    (void)in_sizes; (void)n_in; (void)out_size;
    const float* x    = (const float*)d_in[0];
    // d_in[1] is the boolean tril mask — causal structure is known, unused.
    const float* cosT = (const float*)d_in[2];
    const float* sinT = (const float*)d_in[3];
    const float* Wq   = (const float*)d_in[4];
    const float* Wk   = (const float*)d_in[5];
    const float* Wv   = (const float*)d_in[6];
    const float* Wo   = (const float*)d_in[7];
    float* out = (float*)d_out;

    void* sp = nullptr;
    cudaGetSymbolAddress(&sp, g_scratch);
    float* gQ = (float*)sp;
    const size_t TEN = (size_t)B_ * H_ * T_ * Dh_;   // 8,388,608
    float* gK = gQ + TEN;
    float* gV = gK + TEN;
    float* gA = gV + TEN;

    dim3 gg(DM_ / 128, M_ / 128);   // (16, 32)
    sgemm_kernel<1><<<gg, 256>>>(x, Wq, gQ);
    sgemm_kernel<1><<<gg, 256>>>(x, Wk, gK);
    sgemm_kernel<1><<<gg, 256>>>(x, Wv, gV);

    rope_kernel<<<(2 * B_ * H_ * T_ * 64) / 256, 256>>>(gQ, gK, cosT, sinT);

    const int FA_SMEM = (128 * FPAD * 2 + 64 * 128 + 64 * PPAD) * (int)sizeof(float);
    cudaFuncSetAttribute(flash_kernel,
                         cudaFuncAttributeMaxDynamicSharedMemorySize, FA_SMEM);
    flash_kernel<<<dim3(T_ / 64, B_ * H_), 256, FA_SMEM>>>(gQ, gK, gV, gA);

    sgemm_kernel<0><<<gg, 256>>>(gA, Wo, out);
}

// round 15
// speedup vs baseline: 1.0001x; 1.0001x over previous
#include <cuda_runtime.h>
#include <cstdint>

// Problem constants
#define B_   2
#define T_   2048
#define DM_  2048
#define H_   16
#define Dh_  128
#define M_   (B_ * T_)          // 4096 rows for all GEMMs

// Scratch: Q, K, V, attn-out, each [B,H,T,D] (or [B*T, H*D]) = 8,388,608 floats.
__device__ float g_scratch[4ull * (size_t)B_ * H_ * T_ * Dh_];

// ---------------------------------------------------------------------------
// SGEMM: C[M,N] = A[M,K] @ W[K,N], M=4096, N=K=2048, fp32.
// 128x128 block tile, BK=8, 256 threads, 8x8 per-thread microtile,
// double-buffered smem, register-staged global prefetch.
// MODE 0: C row-major [M, N] (final output projection)
// MODE 1: scatter to [B, H, T, D] layout (QKV; each block-col = one head)
// ---------------------------------------------------------------------------
template<int MODE>
__global__ __launch_bounds__(256)
void sgemm_kernel(const float* __restrict__ A, const float* __restrict__ W,
                  float* __restrict__ C)
{
    constexpr int K  = DM_;        // 2048
    constexpr int N  = DM_;        // 2048
    constexpr int BK = 8;
    constexpr int NK = K / BK;     // 256

    __shared__ __align__(16) float As[2][BK][132];  // transposed A tile, padded
    __shared__ __align__(16) float Bs[2][BK][128];

    const int tid = threadIdx.x;
    const int m0  = blockIdx.y * 128;
    const int n0  = blockIdx.x * 128;

    // Global load mapping
    const int a_row = tid >> 1;           // 0..127
    const int a_col = (tid & 1) * 4;      // 0 or 4
    const int b_row = tid >> 5;           // 0..7
    const int b_col = (tid & 31) * 4;     // 0..124

    const float* Ap = A + (size_t)(m0 + a_row) * K + a_col;
    const float* Wp = W + (size_t)b_row * N + (n0 + b_col);

    // Preload tile 0
    float4 ar = *(const float4*)Ap;
    float4 br = *(const float4*)Wp;
    As[0][a_col + 0][a_row] = ar.x;
    As[0][a_col + 1][a_row] = ar.y;
    As[0][a_col + 2][a_row] = ar.z;
    As[0][a_col + 3][a_row] = ar.w;
    *(float4*)&Bs[0][b_row][b_col] = br;
    __syncthreads();

    const int tx = tid & 15, ty = tid >> 4;

    float acc[8][8];
    #pragma unroll
    for (int i = 0; i < 8; ++i)
        #pragma unroll
        for (int j = 0; j < 8; ++j) acc[i][j] = 0.f;

    for (int kt = 0; kt < NK; ++kt) {
        const int cur = kt & 1;
        if (kt + 1 < NK) {
            ar = *(const float4*)(Ap + (kt + 1) * BK);
            br = *(const float4*)(Wp + (size_t)(kt + 1) * BK * N);
        }
        #pragma unroll
        for (int k = 0; k < BK; ++k) {
            float a_[8], b_[8];
            *(float4*)(a_)     = *(const float4*)&As[cur][k][ty * 4];
            *(float4*)(a_ + 4) = *(const float4*)&As[cur][k][64 + ty * 4];
            *(float4*)(b_)     = *(const float4*)&Bs[cur][k][tx * 4];
            *(float4*)(b_ + 4) = *(const float4*)&Bs[cur][k][64 + tx * 4];
            #pragma unroll
            for (int i = 0; i < 8; ++i)
                #pragma unroll
                for (int j = 0; j < 8; ++j)
                    acc[i][j] = fmaf(a_[i], b_[j], acc[i][j]);
        }
        if (kt + 1 < NK) {
            const int nxt = cur ^ 1;
            As[nxt][a_col + 0][a_row] = ar.x;
            As[nxt][a_col + 1][a_row] = ar.y;
            As[nxt][a_col + 2][a_row] = ar.z;
            As[nxt][a_col + 3][a_row] = ar.w;
            *(float4*)&Bs[nxt][b_row][b_col] = br;
            __syncthreads();
        }
    }

    // Epilogue
    #pragma unroll
    for (int ih = 0; ih < 2; ++ih) {
        #pragma unroll
        for (int i = 0; i < 4; ++i) {
            const int r = m0 + ih * 64 + ty * 4 + i;
            #pragma unroll
            for (int jh = 0; jh < 2; ++jh) {
                const int c = n0 + jh * 64 + tx * 4;
                float4 v;
                v.x = acc[ih * 4 + i][jh * 4 + 0];
                v.y = acc[ih * 4 + i][jh * 4 + 1];
                v.z = acc[ih * 4 + i][jh * 4 + 2];
                v.w = acc[ih * 4 + i][jh * 4 + 3];
                if (MODE == 0) {
                    *(float4*)&C[(size_t)r * N + c] = v;
                } else {
                    const int b = r >> 11;           // T_ = 2048 = 2^11
                    const int t = r & (T_ - 1);
                    const int h = c >> 7;            // Dh_ = 128
                    const int d = c & (Dh_ - 1);
                    *(float4*)&C[(((size_t)(b * H_ + h)) * T_ + t) * Dh_ + d] = v;
                }
            }
        }
    }
}

// ---------------------------------------------------------------------------
// RoPE (in-place) on Q and K in [B,H,T,D] layout. Pair (j, j+64), j in [0,64).
// ---------------------------------------------------------------------------
__global__ __launch_bounds__(256)
void rope_kernel(float* __restrict__ Qm, float* __restrict__ Km,
                 const float* __restrict__ cosT, const float* __restrict__ sinT)
{
    const int idx = blockIdx.x * 256 + threadIdx.x;
    constexpr int PT = B_ * H_ * T_ * 64;          // pairs per tensor
    float* X = (idx < PT) ? Qm : Km;
    const int i  = (idx < PT) ? idx : idx - PT;
    const int j  = i & 63;
    const int t  = (i >> 6) & (T_ - 1);
    const int bh = i >> 17;                        // 2048*64 = 2^17
    const float c = cosT[t * 64 + j];
    const float s = sinT[t * 64 + j];
    const size_t base = ((size_t)bh * T_ + t) * Dh_;
    const float x1 = X[base + j];
    const float x2 = X[base + 64 + j];
    X[base + j]      = fmaf(x1, c, -x2 * s);
    X[base + 64 + j] = fmaf(x1, s,  x2 * c);
}

// ---------------------------------------------------------------------------
// Flash attention, fp32, causal. One block per (q-tile of 64, b*h).
// 256 threads: 16x16 grid; S microtile 4x4 per thread, O microtile 4x8.
// Online softmax stats replicated in registers across each 16-lane row group.
// ---------------------------------------------------------------------------
#define FPAD 68   // padded minor dim for transposed Q/K tiles (16B-aligned rows)
#define PPAD 65   // padded minor dim for transposed P tile

__global__ __launch_bounds__(256, 1)
void flash_kernel(const float* __restrict__ Q, const float* __restrict__ K,
                  const float* __restrict__ V, float* __restrict__ O)
{
    extern __shared__ __align__(16) float sm[];
    float* Qt = sm;                       // [128][FPAD]  (Q^T: [d][q])
    float* Kt = Qt + 128 * FPAD;          // [128][FPAD]  (K^T: [d][k])
    float* Vs = Kt + 128 * FPAD;          // [64][128]    (V row-major)
    float* Pt = Vs + 64 * 128;            // [64][PPAD]   (P^T: [k][q])

    const int tid = threadIdx.x;
    const int tx  = tid & 15, ty = tid >> 4;
    const int ty4 = ty * 4, tx4 = tx * 4, tx8 = tx * 8;
    const int q0  = blockIdx.x * 64;
    const int bh  = blockIdx.y;
    const float* Qb = Q + (size_t)bh * T_ * Dh_;
    const float* Kb = K + (size_t)bh * T_ * Dh_;
    const float* Vb = V + (size_t)bh * T_ * Dh_;

    // Load Q tile transposed into smem
    {
        const int row = tid >> 2, c4 = tid & 3;
        #pragma unroll
        for (int it = 0; it < 8; ++it) {
            const int col = (c4 + it * 4) * 4;
            float4 v = *(const float4*)(Qb + (size_t)(q0 + row) * Dh_ + col);
            Qt[(col + 0) * FPAD + row] = v.x;
            Qt[(col + 1) * FPAD + row] = v.y;
            Qt[(col + 2) * FPAD + row] = v.z;
            Qt[(col + 3) * FPAD + row] = v.w;
        }
    }

    float m_i[4], l_i[4], o[4][8];
    #pragma unroll
    for (int i = 0; i < 4; ++i) {
        m_i[i] = -1e30f; l_i[i] = 0.f;
        #pragma unroll
        for (int j = 0; j < 8; ++j) o[i][j] = 0.f;
    }

    const int   ntiles = blockIdx.x + 1;   // causal: kv tiles 0..qtile
    const float scale  = 0.08838834764831845f;   // 1/sqrt(128)

    for (int kt = 0; kt < ntiles; ++kt) {
        const int kv0 = kt * 64;
        __syncthreads();   // prior iter done reading Kt/Vs/Pt
        {
            const int row = tid >> 2, c4 = tid & 3;
            #pragma unroll
            for (int it = 0; it < 8; ++it) {
                const int col = (c4 + it * 4) * 4;
                float4 v = *(const float4*)(Kb + (size_t)(kv0 + row) * Dh_ + col);
                Kt[(col + 0) * FPAD + row] = v.x;
                Kt[(col + 1) * FPAD + row] = v.y;
                Kt[(col + 2) * FPAD + row] = v.z;
                Kt[(col + 3) * FPAD + row] = v.w;
            }
            const int vrow = tid >> 5, vc4 = (tid & 31) * 4;
            #pragma unroll
            for (int it = 0; it < 8; ++it) {
                float4 v = *(const float4*)(Vb + (size_t)(kv0 + vrow + it * 8) * Dh_ + vc4);
                *(float4*)&Vs[(vrow + it * 8) * Dh_ + vc4] = v;
            }
        }
        __syncthreads();

        // S = Q K^T (4x4 per thread over k=128)
        float s[4][4];
        #pragma unroll
        for (int i = 0; i < 4; ++i)
            #pragma unroll
            for (int j = 0; j < 4; ++j) s[i][j] = 0.f;

        #pragma unroll 4
        for (int kk = 0; kk < 128; ++kk) {
            float qv[4], kv[4];
            *(float4*)qv = *(const float4*)&Qt[kk * FPAD + ty4];
            *(float4*)kv = *(const float4*)&Kt[kk * FPAD + tx4];
            #pragma unroll
            for (int i = 0; i < 4; ++i)
                #pragma unroll
                for (int j = 0; j < 4; ++j)
                    s[i][j] = fmaf(qv[i], kv[j], s[i][j]);
        }

        // scale + causal mask (only the diagonal tile needs masking)
        const bool diag = (kv0 == q0);
        #pragma unroll
        for (int i = 0; i < 4; ++i)
            #pragma unroll
            for (int j = 0; j < 4; ++j) {
                float v = s[i][j] * scale;
                if (diag && (tx4 + j) > (ty4 + i)) v = -1e30f;
                s[i][j] = v;
            }

        // online softmax per row (reduce across the 16 lanes of a row group)
        #pragma unroll
        for (int i = 0; i < 4; ++i) {
            float mt = fmaxf(fmaxf(s[i][0], s[i][1]), fmaxf(s[i][2], s[i][3]));
            #pragma unroll
            for (int off = 8; off > 0; off >>= 1)
                mt = fmaxf(mt, __shfl_xor_sync(0xffffffffu, mt, off, 16));
            const float mnew = fmaxf(m_i[i], mt);
            float sum = 0.f;
            #pragma unroll
            for (int j = 0; j < 4; ++j) {
                const float p = __expf(s[i][j] - mnew);
                s[i][j] = p;
                sum += p;
            }
            #pragma unroll
            for (int off = 8; off > 0; off >>= 1)
                sum += __shfl_xor_sync(0xffffffffu, sum, off, 16);
            const float sc = __expf(m_i[i] - mnew);
            l_i[i] = l_i[i] * sc + sum;
            m_i[i] = mnew;
            #pragma unroll
            for (int j = 0; j < 8; ++j) o[i][j] *= sc;
        }

        // write P transposed
        #pragma unroll
        for (int j = 0; j < 4; ++j)
            #pragma unroll
            for (int i = 0; i < 4; ++i)
                Pt[(tx4 + j) * PPAD + ty4 + i] = s[i][j];
        __syncthreads();

        // O += P @ V  (4x8 per thread over kv=64)
        #pragma unroll 2
        for (int kk = 0; kk < 64; ++kk) {
            float p_[4], v_[8];
            #pragma unroll
            for (int i = 0; i < 4; ++i) p_[i] = Pt[kk * PPAD + ty4 + i];
            *(float4*)(v_)     = *(const float4*)&Vs[kk * Dh_ + tx8];
            *(float4*)(v_ + 4) = *(const float4*)&Vs[kk * Dh_ + tx8 + 4];
            #pragma unroll
            for (int i = 0; i < 4; ++i)
                #pragma unroll
                for (int j = 0; j < 8; ++j)
                    o[i][j] = fmaf(p_[i], v_[j], o[i][j]);
        }
    }

    // write O in [B, T, H*D] layout for the output projection GEMM
    const int b = bh >> 4, h = bh & (H_ - 1);
    #pragma unroll
    for (int i = 0; i < 4; ++i) {
        const float inv = 1.0f / l_i[i];
        const int t = q0 + ty4 + i;
        float* dst = O + ((size_t)(b * T_ + t)) * (H_ * Dh_) + h * Dh_ + tx8;
        float4 r0, r1;
        r0.x = o[i][0] * inv; r0.y = o[i][1] * inv;
        r0.z = o[i][2] * inv; r0.w = o[i][3] * inv;
        r1.x = o[i][4] * inv; r1.y = o[i][5] * inv;
        r1.z = o[i][6] * inv; r1.w = o[i][7] * inv;
        *(float4*)dst       = r0;
        *(float4*)(dst + 4) = r1;
    }
}

// ---------------------------------------------------------------------------
// Launch: QKV GEMMs -> RoPE -> flash attention -> output GEMM.
// Graph-capturable: kernel launches + host-side queries only.
// ---------------------------------------------------------------------------
extern "C" void kernel_launch(void* const* d_in, const int* in_sizes, int n_in,
                              void* d_out, int out_size)
{
    (void)in_sizes; (void)n_in; (void)out_size;
    const float* x    = (const float*)d_in[0];
    // d_in[1] is the boolean tril mask — causal structure is known, unused.
    const float* cosT = (const float*)d_in[2];
    const float* sinT = (const float*)d_in[3];
    const float* Wq   = (const float*)d_in[4];
    const float* Wk   = (const float*)d_in[5];
    const float* Wv   = (const float*)d_in[6];
    const float* Wo   = (const float*)d_in[7];
    float* out = (float*)d_out;

    void* sp = nullptr;
    cudaGetSymbolAddress(&sp, g_scratch);
    float* gQ = (float*)sp;
    const size_t TEN = (size_t)B_ * H_ * T_ * Dh_;   // 8,388,608
    float* gK = gQ + TEN;
    float* gV = gK + TEN;
    float* gA = gV + TEN;

    dim3 gg(DM_ / 128, M_ / 128);   // (16, 32)
    sgemm_kernel<1><<<gg, 256>>>(x, Wq, gQ);
    sgemm_kernel<1><<<gg, 256>>>(x, Wk, gK);
    sgemm_kernel<1><<<gg, 256>>>(x, Wv, gV);

    rope_kernel<<<(2 * B_ * H_ * T_ * 64) / 256, 256>>>(gQ, gK, cosT, sinT);

    const int FA_SMEM = (128 * FPAD * 2 + 64 * 128 + 64 * PPAD) * (int)sizeof(float);
    cudaFuncSetAttribute(flash_kernel,
                         cudaFuncAttributeMaxDynamicSharedMemorySize, FA_SMEM);
    flash_kernel<<<dim3(T_ / 64, B_ * H_), 256, FA_SMEM>>>(gQ, gK, gV, gA);

    sgemm_kernel<0><<<gg, 256>>>(gA, Wo, out);
}

// round 16
// speedup vs baseline: 1.6468x; 1.6466x over previous
#include <cuda_runtime.h>
#include <cstdint>

// Problem constants
#define B_   2
#define T_   2048
#define DM_  2048
#define H_   16
#define Dh_  128
#define M_   (B_ * T_)          // 4096 rows for all GEMMs

// Scratch: Q, K, V, attn-out, each [B,H,T,D] (or [B*T, H*D]) = 8,388,608 floats.
__device__ float g_scratch[4ull * (size_t)B_ * H_ * T_ * Dh_];

__device__ __forceinline__ float cvt_tf32(float x) {
    uint32_t o;
    asm("cvt.rna.tf32.f32 %0, %1;" : "=r"(o) : "f"(x));
    return __uint_as_float(o);
}

__device__ __forceinline__ void mma_tf32(float* d, const uint32_t* a, const uint32_t* b) {
    asm volatile(
        "mma.sync.aligned.m16n8k8.row.col.f32.tf32.tf32.f32 "
        "{%0,%1,%2,%3},{%4,%5,%6,%7},{%8,%9},{%0,%1,%2,%3};"
        : "+f"(d[0]), "+f"(d[1]), "+f"(d[2]), "+f"(d[3])
        : "r"(a[0]), "r"(a[1]), "r"(a[2]), "r"(a[3]), "r"(b[0]), "r"(b[1]));
}

// ---------------------------------------------------------------------------
// Tensor-core GEMM (tf32 mma.sync): C[M,N] = A[M,K] @ W[K,N], M=4096, N=K=2048.
// 128x128x32 block tile, 256 threads (8 warps, 4x2), warp tile 32x64 =
// 2x8 m16n8k8 tiles. Double-buffered smem, stride 136 (8 mod 32) for
// conflict-free fragment loads. fp32 accumulate.
// MODE 0: C row-major [M, N];  MODE 1: scatter to [B, H, T, D].
// ---------------------------------------------------------------------------
#define GLDS 136
#define GBUF (32 * GLDS)   // floats per (As or Bs) buffer

template<int MODE>
__global__ __launch_bounds__(256)
void mma_gemm_kernel(const float* __restrict__ A, const float* __restrict__ W,
                     float* __restrict__ C)
{
    constexpr int K  = DM_;
    constexpr int N  = DM_;
    constexpr int BK = 32;
    constexpr int NK = K / BK;     // 64

    extern __shared__ __align__(16) float gsm[];
    float* AsBuf = gsm;                 // [2][32][136]  A^T: [k][m]
    float* BsBuf = gsm + 2 * GBUF;      // [2][32][136]  W:   [k][n]

    const int tid = threadIdx.x;
    const int m0  = blockIdx.y * 128;
    const int n0  = blockIdx.x * 128;

    // Global load mapping
    const int a_row = tid >> 1;           // 0..127
    const int a_k0  = (tid & 1) * 16;     // 0 or 16
    const int w_k   = tid >> 3;           // 0..31
    const int w_c0  = (tid & 7) * 4;      // 0..28

    const float* Ap = A + (size_t)(m0 + a_row) * K + a_k0;
    const float* Wp = W + (size_t)w_k * N + n0 + w_c0;

    float4 ar[4], wr[4];

    // Preload tile 0
    #pragma unroll
    for (int i = 0; i < 4; ++i) ar[i] = *(const float4*)(Ap + i * 4);
    #pragma unroll
    for (int j = 0; j < 4; ++j) wr[j] = *(const float4*)(Wp + j * 32);
    {
        float* Asb = AsBuf;
        float* Bsb = BsBuf;
        #pragma unroll
        for (int i = 0; i < 4; ++i) {
            const int k = a_k0 + i * 4;
            Asb[(k + 0) * GLDS + a_row] = cvt_tf32(ar[i].x);
            Asb[(k + 1) * GLDS + a_row] = cvt_tf32(ar[i].y);
            Asb[(k + 2) * GLDS + a_row] = cvt_tf32(ar[i].z);
            Asb[(k + 3) * GLDS + a_row] = cvt_tf32(ar[i].w);
        }
        #pragma unroll
        for (int j = 0; j < 4; ++j) {
            float4 v;
            v.x = cvt_tf32(wr[j].x); v.y = cvt_tf32(wr[j].y);
            v.z = cvt_tf32(wr[j].z); v.w = cvt_tf32(wr[j].w);
            *(float4*)&Bsb[w_k * GLDS + w_c0 + j * 32] = v;
        }
    }
    __syncthreads();

    const int lane = tid & 31;
    const int gid  = lane >> 2;     // 0..7
    const int tig  = lane & 3;      // 0..3
    const int warp = tid >> 5;
    const int wm   = (warp & 3) * 32;    // warp m base within block
    const int wn   = (warp >> 2) * 64;   // warp n base within block

    float acc[2][8][4];
    #pragma unroll
    for (int mt = 0; mt < 2; ++mt)
        #pragma unroll
        for (int nt = 0; nt < 8; ++nt)
            #pragma unroll
            for (int r = 0; r < 4; ++r) acc[mt][nt][r] = 0.f;

    for (int kt = 0; kt < NK; ++kt) {
        const int cur = kt & 1;
        if (kt + 1 < NK) {
            #pragma unroll
            for (int i = 0; i < 4; ++i)
                ar[i] = *(const float4*)(Ap + (size_t)(kt + 1) * BK + i * 4);
            #pragma unroll
            for (int j = 0; j < 4; ++j)
                wr[j] = *(const float4*)(Wp + (size_t)(kt + 1) * BK * N + j * 32);
        }

        const float* Ab = AsBuf + cur * GBUF;
        const float* Bb = BsBuf + cur * GBUF;

        #pragma unroll
        for (int ks = 0; ks < 4; ++ks) {
            const int kk = ks * 8 + tig;
            uint32_t af[2][4], bf[8][2];
            #pragma unroll
            for (int mt = 0; mt < 2; ++mt) {
                const int m = wm + mt * 16 + gid;
                af[mt][0] = __float_as_uint(Ab[kk * GLDS + m]);
                af[mt][1] = __float_as_uint(Ab[kk * GLDS + m + 8]);
                af[mt][2] = __float_as_uint(Ab[(kk + 4) * GLDS + m]);
                af[mt][3] = __float_as_uint(Ab[(kk + 4) * GLDS + m + 8]);
            }
            #pragma unroll
            for (int nt = 0; nt < 8; ++nt) {
                const int n = wn + nt * 8 + gid;
                bf[nt][0] = __float_as_uint(Bb[kk * GLDS + n]);
                bf[nt][1] = __float_as_uint(Bb[(kk + 4) * GLDS + n]);
            }
            #pragma unroll
            for (int mt = 0; mt < 2; ++mt)
                #pragma unroll
                for (int nt = 0; nt < 8; ++nt)
                    mma_tf32(acc[mt][nt], af[mt], bf[nt]);
        }

        if (kt + 1 < NK) {
            const int nxt = cur ^ 1;
            float* Asb = AsBuf + nxt * GBUF;
            float* Bsb = BsBuf + nxt * GBUF;
            #pragma unroll
            for (int i = 0; i < 4; ++i) {
                const int k = a_k0 + i * 4;
                Asb[(k + 0) * GLDS + a_row] = cvt_tf32(ar[i].x);
                Asb[(k + 1) * GLDS + a_row] = cvt_tf32(ar[i].y);
                Asb[(k + 2) * GLDS + a_row] = cvt_tf32(ar[i].z);
                Asb[(k + 3) * GLDS + a_row] = cvt_tf32(ar[i].w);
            }
            #pragma unroll
            for (int j = 0; j < 4; ++j) {
                float4 v;
                v.x = cvt_tf32(wr[j].x); v.y = cvt_tf32(wr[j].y);
                v.z = cvt_tf32(wr[j].z); v.w = cvt_tf32(wr[j].w);
                *(float4*)&Bsb[w_k * GLDS + w_c0 + j * 32] = v;
            }
            __syncthreads();
        }
    }

    // Epilogue. c0:(gid, 2tig) c1:(gid, 2tig+1) c2:(gid+8, 2tig) c3:(gid+8, 2tig+1)
    #pragma unroll
    for (int mt = 0; mt < 2; ++mt) {
        const int r0 = m0 + wm + mt * 16 + gid;     // block rows don't straddle b
        #pragma unroll
        for (int nt = 0; nt < 8; ++nt) {
            const int dcol = wn + nt * 8 + 2 * tig;     // 0..126, even
            float2 lo, hi;
            lo.x = acc[mt][nt][0]; lo.y = acc[mt][nt][1];
            hi.x = acc[mt][nt][2]; hi.y = acc[mt][nt][3];
            if (MODE == 0) {
                const int c = n0 + dcol;
                *(float2*)&C[(size_t)r0 * N + c]       = lo;
                *(float2*)&C[(size_t)(r0 + 8) * N + c] = hi;
            } else {
                const int h = n0 >> 7;              // whole 128-col block = 1 head
                const int b = r0 >> 11;
                const int t = r0 & (T_ - 1);
                float* base = C + (((size_t)(b * H_ + h)) * T_) * Dh_;
                *(float2*)&base[(size_t)t * Dh_ + dcol]       = lo;
                *(float2*)&base[(size_t)(t + 8) * Dh_ + dcol] = hi;
            }
        }
    }
}

#define GEMM_SMEM (4 * GBUF * (int)sizeof(float))   // 69632 bytes

// ---------------------------------------------------------------------------
// RoPE (in-place) on Q and K in [B,H,T,D] layout. Pair (j, j+64), j in [0,64).
// ---------------------------------------------------------------------------
__global__ __launch_bounds__(256)
void rope_kernel(float* __restrict__ Qm, float* __restrict__ Km,
                 const float* __restrict__ cosT, const float* __restrict__ sinT)
{
    const int idx = blockIdx.x * 256 + threadIdx.x;
    constexpr int PT = B_ * H_ * T_ * 64;          // pairs per tensor
    float* X = (idx < PT) ? Qm : Km;
    const int i  = (idx < PT) ? idx : idx - PT;
    const int j  = i & 63;
    const int t  = (i >> 6) & (T_ - 1);
    const int bh = i >> 17;                        // 2048*64 = 2^17
    const float c = cosT[t * 64 + j];
    const float s = sinT[t * 64 + j];
    const size_t base = ((size_t)bh * T_ + t) * Dh_;
    const float x1 = X[base + j];
    const float x2 = X[base + 64 + j];
    X[base + j]      = fmaf(x1, c, -x2 * s);
    X[base + 64 + j] = fmaf(x1, s,  x2 * c);
}

// ---------------------------------------------------------------------------
// Flash attention, fp32, causal. One block per (q-tile of 64, b*h).
// 256 threads: 16x16 grid; S microtile 4x4 per thread, O microtile 4x8.
// Online softmax stats replicated in registers across each 16-lane row group.
// ---------------------------------------------------------------------------
#define FPAD 68   // padded minor dim for transposed Q/K tiles (16B-aligned rows)
#define PPAD 65   // padded minor dim for transposed P tile

__global__ __launch_bounds__(256, 1)
void flash_kernel(const float* __restrict__ Q, const float* __restrict__ K,
                  const float* __restrict__ V, float* __restrict__ O)
{
    extern __shared__ __align__(16) float sm[];
    float* Qt = sm;                       // [128][FPAD]  (Q^T: [d][q])
    float* Kt = Qt + 128 * FPAD;          // [128][FPAD]  (K^T: [d][k])
    float* Vs = Kt + 128 * FPAD;          // [64][128]    (V row-major)
    float* Pt = Vs + 64 * 128;            // [64][PPAD]   (P^T: [k][q])

    const int tid = threadIdx.x;
    const int tx  = tid & 15, ty = tid >> 4;
    const int ty4 = ty * 4, tx4 = tx * 4, tx8 = tx * 8;
    const int q0  = blockIdx.x * 64;
    const int bh  = blockIdx.y;
    const float* Qb = Q + (size_t)bh * T_ * Dh_;
    const float* Kb = K + (size_t)bh * T_ * Dh_;
    const float* Vb = V + (size_t)bh * T_ * Dh_;

    // Load Q tile transposed into smem
    {
        const int row = tid >> 2, c4 = tid & 3;
        #pragma unroll
        for (int it = 0; it < 8; ++it) {
            const int col = (c4 + it * 4) * 4;
            float4 v = *(const float4*)(Qb + (size_t)(q0 + row) * Dh_ + col);
            Qt[(col + 0) * FPAD + row] = v.x;
            Qt[(col + 1) * FPAD + row] = v.y;
            Qt[(col + 2) * FPAD + row] = v.z;
            Qt[(col + 3) * FPAD + row] = v.w;
        }
    }

    float m_i[4], l_i[4], o[4][8];
    #pragma unroll
    for (int i = 0; i < 4; ++i) {
        m_i[i] = -1e30f; l_i[i] = 0.f;
        #pragma unroll
        for (int j = 0; j < 8; ++j) o[i][j] = 0.f;
    }

    const int   ntiles = blockIdx.x + 1;   // causal: kv tiles 0..qtile
    const float scale  = 0.08838834764831845f;   // 1/sqrt(128)

    for (int kt = 0; kt < ntiles; ++kt) {
        const int kv0 = kt * 64;
        __syncthreads();   // prior iter done reading Kt/Vs/Pt
        {
            const int row = tid >> 2, c4 = tid & 3;
            #pragma unroll
            for (int it = 0; it < 8; ++it) {
                const int col = (c4 + it * 4) * 4;
                float4 v = *(const float4*)(Kb + (size_t)(kv0 + row) * Dh_ + col);
                Kt[(col + 0) * FPAD + row] = v.x;
                Kt[(col + 1) * FPAD + row] = v.y;
                Kt[(col + 2) * FPAD + row] = v.z;
                Kt[(col + 3) * FPAD + row] = v.w;
            }
            const int vrow = tid >> 5, vc4 = (tid & 31) * 4;
            #pragma unroll
            for (int it = 0; it < 8; ++it) {
                float4 v = *(const float4*)(Vb + (size_t)(kv0 + vrow + it * 8) * Dh_ + vc4);
                *(float4*)&Vs[(vrow + it * 8) * Dh_ + vc4] = v;
            }
        }
        __syncthreads();

        // S = Q K^T (4x4 per thread over k=128)
        float s[4][4];
        #pragma unroll
        for (int i = 0; i < 4; ++i)
            #pragma unroll
            for (int j = 0; j < 4; ++j) s[i][j] = 0.f;

        #pragma unroll 4
        for (int kk = 0; kk < 128; ++kk) {
            float qv[4], kv[4];
            *(float4*)qv = *(const float4*)&Qt[kk * FPAD + ty4];
            *(float4*)kv = *(const float4*)&Kt[kk * FPAD + tx4];
            #pragma unroll
            for (int i = 0; i < 4; ++i)
                #pragma unroll
                for (int j = 0; j < 4; ++j)
                    s[i][j] = fmaf(qv[i], kv[j], s[i][j]);
        }

        // scale + causal mask (only the diagonal tile needs masking)
        const bool diag = (kv0 == q0);
        #pragma unroll
        for (int i = 0; i < 4; ++i)
            #pragma unroll
            for (int j = 0; j < 4; ++j) {
                float v = s[i][j] * scale;
                if (diag && (tx4 + j) > (ty4 + i)) v = -1e30f;
                s[i][j] = v;
            }

        // online softmax per row (reduce across the 16 lanes of a row group)
        #pragma unroll
        for (int i = 0; i < 4; ++i) {
            float mt = fmaxf(fmaxf(s[i][0], s[i][1]), fmaxf(s[i][2], s[i][3]));
            #pragma unroll
            for (int off = 8; off > 0; off >>= 1)
                mt = fmaxf(mt, __shfl_xor_sync(0xffffffffu, mt, off, 16));
            const float mnew = fmaxf(m_i[i], mt);
            float sum = 0.f;
            #pragma unroll
            for (int j = 0; j < 4; ++j) {
                const float p = __expf(s[i][j] - mnew);
                s[i][j] = p;
                sum += p;
            }
            #pragma unroll
            for (int off = 8; off > 0; off >>= 1)
                sum += __shfl_xor_sync(0xffffffffu, sum, off, 16);
            const float sc = __expf(m_i[i] - mnew);
            l_i[i] = l_i[i] * sc + sum;
            m_i[i] = mnew;
            #pragma unroll
            for (int j = 0; j < 8; ++j) o[i][j] *= sc;
        }

        // write P transposed
        #pragma unroll
        for (int j = 0; j < 4; ++j)
            #pragma unroll
            for (int i = 0; i < 4; ++i)
                Pt[(tx4 + j) * PPAD + ty4 + i] = s[i][j];
        __syncthreads();

        // O += P @ V  (4x8 per thread over kv=64)
        #pragma unroll 2
        for (int kk = 0; kk < 64; ++kk) {
            float p_[4], v_[8];
            #pragma unroll
            for (int i = 0; i < 4; ++i) p_[i] = Pt[kk * PPAD + ty4 + i];
            *(float4*)(v_)     = *(const float4*)&Vs[kk * Dh_ + tx8];
            *(float4*)(v_ + 4) = *(const float4*)&Vs[kk * Dh_ + tx8 + 4];
            #pragma unroll
            for (int i = 0; i < 4; ++i)
                #pragma unroll
                for (int j = 0; j < 8; ++j)
                    o[i][j] = fmaf(p_[i], v_[j], o[i][j]);
        }
    }

    // write O in [B, T, H*D] layout for the output projection GEMM
    const int b = bh >> 4, h = bh & (H_ - 1);
    #pragma unroll
    for (int i = 0; i < 4; ++i) {
        const float inv = 1.0f / l_i[i];
        const int t = q0 + ty4 + i;
        float* dst = O + ((size_t)(b * T_ + t)) * (H_ * Dh_) + h * Dh_ + tx8;
        float4 r0, r1;
        r0.x = o[i][0] * inv; r0.y = o[i][1] * inv;
        r0.z = o[i][2] * inv; r0.w = o[i][3] * inv;
        r1.x = o[i][4] * inv; r1.y = o[i][5] * inv;
        r1.z = o[i][6] * inv; r1.w = o[i][7] * inv;
        *(float4*)dst       = r0;
        *(float4*)(dst + 4) = r1;
    }
}

// ---------------------------------------------------------------------------
// Launch: QKV GEMMs (tf32 mma) -> RoPE -> flash attention -> output GEMM.
// Graph-capturable: kernel launches + host-side attribute/query calls only.
// ---------------------------------------------------------------------------
extern "C" void kernel_launch(void* const* d_in, const int* in_sizes, int n_in,
                              void* d_out, int out_size)
{
    (void)in_sizes; (void)n_in; (void)out_size;
    const float* x    = (const float*)d_in[0];
    // d_in[1] is the boolean tril mask — causal structure is known, unused.
    const float* cosT = (const float*)d_in[2];
    const float* sinT = (const float*)d_in[3];
    const float* Wq   = (const float*)d_in[4];
    const float* Wk   = (const float*)d_in[5];
    const float* Wv   = (const float*)d_in[6];
    const float* Wo   = (const float*)d_in[7];
    float* out = (float*)d_out;

    void* sp = nullptr;
    cudaGetSymbolAddress(&sp, g_scratch);
    float* gQ = (float*)sp;
    const size_t TEN = (size_t)B_ * H_ * T_ * Dh_;   // 8,388,608
    float* gK = gQ + TEN;
    float* gV = gK + TEN;
    float* gA = gV + TEN;

    cudaFuncSetAttribute(mma_gemm_kernel<0>,
                         cudaFuncAttributeMaxDynamicSharedMemorySize, GEMM_SMEM);
    cudaFuncSetAttribute(mma_gemm_kernel<1>,
                         cudaFuncAttributeMaxDynamicSharedMemorySize, GEMM_SMEM);

    dim3 gg(DM_ / 128, M_ / 128);   // (16, 32)
    mma_gemm_kernel<1><<<gg, 256, GEMM_SMEM>>>(x, Wq, gQ);
    mma_gemm_kernel<1><<<gg, 256, GEMM_SMEM>>>(x, Wk, gK);
    mma_gemm_kernel<1><<<gg, 256, GEMM_SMEM>>>(x, Wv, gV);

    rope_kernel<<<(2 * B_ * H_ * T_ * 64) / 256, 256>>>(gQ, gK, cosT, sinT);

    const int FA_SMEM = (128 * FPAD * 2 + 64 * 128 + 64 * PPAD) * (int)sizeof(float);
    cudaFuncSetAttribute(flash_kernel,
                         cudaFuncAttributeMaxDynamicSharedMemorySize, FA_SMEM);
    flash_kernel<<<dim3(T_ / 64, B_ * H_), 256, FA_SMEM>>>(gQ, gK, gV, gA);

    mma_gemm_kernel<0><<<gg, 256, GEMM_SMEM>>>(gA, Wo, out);
}